// round 2
// baseline (speedup 1.0000x reference)
#include <cuda_runtime.h>

#define NB 16384
#define HD 768

// ---------------- scratch (device globals; no allocs allowed) ----------------
__device__ float g_scrA[NB * 768];   // 48 MB
__device__ float g_scrB[NB * 384];   // 24 MB
__device__ float g_scrC[NB * 256];   // 16 MB
__device__ float g_scrD[NB * 64];    //  4 MB
__device__ float g_norm[2 * NB];     // norms of image_feat, text_feat

// ---------------- helpers ----------------
__device__ __forceinline__ float sigf(float x) { return 1.0f / (1.0f + expf(-x)); }
__device__ __forceinline__ float geluf(float x) { return 0.5f * x * (1.0f + erff(x * 0.70710678118654752f)); }

__device__ __forceinline__ unsigned long long pack2b(float x) {
    unsigned long long r;
    asm("mov.b64 %0, {%1, %1};" : "=l"(r) : "f"(x));
    return r;
}
__device__ __forceinline__ void unpack2(unsigned long long v, float& x, float& y) {
    asm("mov.b64 {%0, %1}, %2;" : "=f"(x), "=f"(y) : "l"(v));
}
__device__ __forceinline__ void ffma2(unsigned long long& d, unsigned long long a, unsigned long long b) {
    asm("fma.rn.f32x2 %0, %1, %2, %0;" : "+l"(d) : "l"(a), "l"(b));
}

// ---------------- GEMM: C[M,N] = act(A @ W + bias) ----------------
// A given as two halves (concat support): row stride Khalf each.
// BM=128, BN=64, BK=16, 256 threads, thread tile 8(M as 4 f32x2 pairs) x 4(N).
__global__ __launch_bounds__(256) void gemm_k(
    const float* __restrict__ A1, const float* __restrict__ A2,
    int Khalf, int Ktot,
    const float* __restrict__ W, int N,
    const float* __restrict__ bias,
    float* __restrict__ C, int act)
{
    __shared__ float As[16 * 130];
    __shared__ float Bs[16 * 64];
    const int t  = threadIdx.x;
    const int tx = t & 15;        // N groups of 4
    const int ty = t >> 4;        // M groups of 8
    const int n0 = blockIdx.x * 64;
    const int m0 = blockIdx.y * 128;

    unsigned long long acc[4][4];
#pragma unroll
    for (int i = 0; i < 4; i++)
#pragma unroll
        for (int j = 0; j < 4; j++) acc[i][j] = 0ull;

    for (int k0 = 0; k0 < Ktot; k0 += 16) {
        const float* Abase;
        int kk;
        if (k0 < Khalf) { Abase = A1; kk = k0; }
        else            { Abase = A2; kk = k0 - Khalf; }

        // load A tile [128 x 16] -> As transposed [16][130]
#pragma unroll
        for (int l = 0; l < 2; l++) {
            int idx = t + l * 256;      // 0..511
            int r   = idx >> 2;         // row 0..127
            int c4  = (idx & 3) * 4;    // col 0,4,8,12
            float4 v = *reinterpret_cast<const float4*>(Abase + (size_t)(m0 + r) * Khalf + kk + c4);
            As[(c4 + 0) * 130 + r] = v.x;
            As[(c4 + 1) * 130 + r] = v.y;
            As[(c4 + 2) * 130 + r] = v.z;
            As[(c4 + 3) * 130 + r] = v.w;
        }
        // load B tile [16 x 64]
        {
            int r = t >> 4;
            int c = (t & 15) * 4;
            float4 v = *reinterpret_cast<const float4*>(W + (size_t)(k0 + r) * N + n0 + c);
            *reinterpret_cast<float4*>(&Bs[r * 64 + c]) = v;
        }
        __syncthreads();

#pragma unroll
        for (int k = 0; k < 16; k++) {
            unsigned long long a2[4];
            const unsigned long long* pA =
                reinterpret_cast<const unsigned long long*>(&As[k * 130 + ty * 8]);
            a2[0] = pA[0]; a2[1] = pA[1]; a2[2] = pA[2]; a2[3] = pA[3];
            float4 bv = *reinterpret_cast<const float4*>(&Bs[k * 64 + tx * 4]);
            unsigned long long b2[4];
            b2[0] = pack2b(bv.x); b2[1] = pack2b(bv.y);
            b2[2] = pack2b(bv.z); b2[3] = pack2b(bv.w);
#pragma unroll
            for (int i = 0; i < 4; i++)
#pragma unroll
                for (int j = 0; j < 4; j++) ffma2(acc[i][j], a2[i], b2[j]);
        }
        __syncthreads();
    }

    // epilogue
    float bb[4];
#pragma unroll
    for (int j = 0; j < 4; j++) bb[j] = bias[n0 + tx * 4 + j];

#pragma unroll
    for (int i = 0; i < 4; i++) {
        int m = m0 + ty * 8 + i * 2;
        float lo[4], hi[4];
#pragma unroll
        for (int j = 0; j < 4; j++) {
            unpack2(acc[i][j], lo[j], hi[j]);
            lo[j] += bb[j];
            hi[j] += bb[j];
            if (act == 1) { lo[j] = geluf(lo[j]); hi[j] = geluf(hi[j]); }
        }
        float4 r0 = make_float4(lo[0], lo[1], lo[2], lo[3]);
        float4 r1 = make_float4(hi[0], hi[1], hi[2], hi[3]);
        *reinterpret_cast<float4*>(C + (size_t)m * N + n0 + tx * 4)       = r0;
        *reinterpret_cast<float4*>(C + (size_t)(m + 1) * N + n0 + tx * 4) = r1;
    }
}

// ---------------- final dot head: out[m] = sigmoid(H[m,:] . w + b) ----------------
__global__ void dot_head_k(const float* __restrict__ Hin, int K,
                           const float* __restrict__ w, const float* __restrict__ b,
                           float* __restrict__ outrow)
{
    int gw   = (blockIdx.x * blockDim.x + threadIdx.x) >> 5;
    int lane = threadIdx.x & 31;
    if (gw >= NB) return;
    const float* row = Hin + (size_t)gw * K;
    float s = 0.f;
    for (int k = lane * 4; k < K; k += 128) {
        float4 v  = *reinterpret_cast<const float4*>(row + k);
        float4 wv = *reinterpret_cast<const float4*>(w + k);
        s += v.x * wv.x + v.y * wv.y + v.z * wv.z + v.w * wv.w;
    }
#pragma unroll
    for (int o = 16; o; o >>= 1) s += __shfl_xor_sync(0xffffffffu, s, o);
    if (lane == 0) outrow[gw] = sigf(s + b[0]);
}

// ---------------- geometric quality (rows 0..3) + norms ----------------
__global__ void rowstats_k(const float* __restrict__ f0, const float* __restrict__ f1,
                           const float* __restrict__ f2, const float* __restrict__ f3,
                           float* __restrict__ out)
{
    int gw   = (blockIdx.x * blockDim.x + threadIdx.x) >> 5;
    int lane = threadIdx.x & 31;
    if (gw >= 4 * NB) return;
    int feat = gw >> 14;
    int m    = gw & (NB - 1);
    const float* f = (feat == 0 ? f0 : feat == 1 ? f1 : feat == 2 ? f2 : f3) + (size_t)m * HD;

    double sum = 0.0, ssq = 0.0;
    int cnt = 0;
    for (int k = lane * 4; k < HD; k += 128) {
        float4 v = *reinterpret_cast<const float4*>(f + k);
        sum += (double)v.x + v.y + v.z + v.w;
        ssq += (double)v.x * v.x + (double)v.y * v.y + (double)v.z * v.z + (double)v.w * v.w;
        cnt += (fabsf(v.x) > 0.01f) + (fabsf(v.y) > 0.01f) + (fabsf(v.z) > 0.01f) + (fabsf(v.w) > 0.01f);
    }
#pragma unroll
    for (int o = 16; o; o >>= 1) {
        sum += __shfl_xor_sync(0xffffffffu, sum, o);
        ssq += __shfl_xor_sync(0xffffffffu, ssq, o);
        cnt += __shfl_xor_sync(0xffffffffu, cnt, o);
    }
    if (lane == 0) {
        float n   = (float)sqrt(ssq);
        float nq  = sigf((n - 1.0f) * 2.0f);
        float sp  = cnt * (1.0f / 768.0f);
        double var = (ssq - sum * sum / 768.0) / 767.0;
        if (var < 0.0) var = 0.0;
        float sq  = sigf((float)sqrt(var) * 10.0f - 1.0f);
        out[feat * NB + m] = (nq + sp + sq) * (1.0f / 3.0f);
        if (feat < 2) g_norm[feat * NB + m] = n;
    }
}

// ---------------- information quality final (entropy etc.) ----------------
__global__ void info_final_k(const float* __restrict__ enc, int fi, float* __restrict__ outrow)
{
    int gw   = (blockIdx.x * blockDim.x + threadIdx.x) >> 5;
    int lane = threadIdx.x & 31;
    if (gw >= NB) return;
    const float* e = enc + (size_t)gw * 64;
    float x0 = e[lane], x1 = e[lane + 32];
    int d0 = (int)rintf(sigf(x0) * 10.0f);  // round-half-even, matches jnp.round
    int d1 = (int)rintf(sigf(x1) * 10.0f);
    float ent = 0.f;
#pragma unroll
    for (int b = 0; b < 11; b++) {
        int c = __popc(__ballot_sync(0xffffffffu, d0 == b)) +
                __popc(__ballot_sync(0xffffffffu, d1 == b));
        if (c > 0) {
            float p = c * (1.0f / 64.0f);
            ent -= p * logf(p + 1e-8f);
        }
    }
    if (lane == 0) {
        float eq = sigf(ent - 2.0f);
        float n  = g_norm[fi * NB + gw];
        float cq = (n > 0.01f) ? (1.0f / 768.0f) : 0.0f;
        float t  = n / fmaxf(n, 1e-12f);
        float dq = sigf(t * t - 0.5f);
        outrow[gw] = (eq + cq + dq) * (1.0f / 3.0f);
    }
}

// ---------------- overall (row 17) ----------------
__global__ void overall_k(float* __restrict__ out)
{
    int i = blockIdx.x * blockDim.x + threadIdx.x;
    if (i >= NB) return;
    float v = out[0 * NB + i] + out[1 * NB + i] + out[4 * NB + i] + out[5 * NB + i] +
              out[7 * NB + i] + 0.5f * (out[8 * NB + i] + out[9 * NB + i]);
    out[17 * NB + i] = v * (1.0f / 6.0f);
}

// ---------------- host ----------------
static inline void launch_gemm(const float* A1, const float* A2, int Khalf, int Ktot,
                               const float* W, int N, const float* bias, float* C, int act)
{
    dim3 grid(N / 64, NB / 128);
    gemm_k<<<grid, 256>>>(A1, A2 ? A2 : A1, Khalf, Ktot, W, N, bias, C, act);
}

extern "C" void kernel_launch(void* const* d_in, const int* in_sizes, int n_in,
                              void* d_out, int out_size)
{
    const float* img  = (const float*)d_in[0];
    const float* txt  = (const float*)d_in[1];
    const float* eimg = (const float*)d_in[2];
    const float* etxt = (const float*)d_in[3];
    // d_in[4] = missing_type (unused)
    const float* info_w1 = (const float*)d_in[5];
    const float* info_b1 = (const float*)d_in[6];
    const float* info_w2 = (const float*)d_in[7];
    const float* info_b2 = (const float*)d_in[8];
    const float* imp_w1  = (const float*)d_in[9];
    const float* imp_b1  = (const float*)d_in[10];
    const float* imp_w2  = (const float*)d_in[11];
    const float* imp_b2  = (const float*)d_in[12];
    const float* disc_w1 = (const float*)d_in[13];
    const float* disc_b1 = (const float*)d_in[14];
    const float* disc_w2 = (const float*)d_in[15];
    const float* disc_b2 = (const float*)d_in[16];
    const float* disc_w3 = (const float*)d_in[17];
    const float* disc_b3 = (const float*)d_in[18];
    const float* cons_w1 = (const float*)d_in[19];
    const float* cons_b1 = (const float*)d_in[20];
    const float* cons_w2 = (const float*)d_in[21];
    const float* cons_b2 = (const float*)d_in[22];
    const float* cons_w3 = (const float*)d_in[23];
    const float* cons_b3 = (const float*)d_in[24];
    const float* diff_w1 = (const float*)d_in[25];
    const float* diff_b1 = (const float*)d_in[26];
    const float* diff_w2 = (const float*)d_in[27];
    const float* diff_b2 = (const float*)d_in[28];
    const float* diff_w3 = (const float*)d_in[29];
    const float* diff_b3 = (const float*)d_in[30];

    float* out = (float*)d_out;

    float *scrA, *scrB, *scrC, *scrD;
    cudaGetSymbolAddress((void**)&scrA, g_scrA);
    cudaGetSymbolAddress((void**)&scrB, g_scrB);
    cudaGetSymbolAddress((void**)&scrC, g_scrC);
    cudaGetSymbolAddress((void**)&scrD, g_scrD);

    const int GELU = 1, LIN = 0;

    // geometric (rows 0..3) + norms for info
    rowstats_k<<<(4 * NB) / 8, 256>>>(img, txt, eimg, etxt, out);

    // information (rows 4,5)
    const float* infeats[2] = { img, txt };
    for (int i = 0; i < 2; i++) {
        launch_gemm(infeats[i], nullptr, 768, 768, info_w1, 256, info_b1, scrC, GELU);
        launch_gemm(scrC, nullptr, 256, 256, info_w2, 64, info_b2, scrD, LIN);
        info_final_k<<<NB / 8, 256>>>(scrD, i, out + (4 + i) * NB);
    }

    // importance (rows 8..11): img, txt, eimg, etxt
    const float* impfeats[4] = { img, txt, eimg, etxt };
    for (int i = 0; i < 4; i++) {
        launch_gemm(impfeats[i], nullptr, 768, 768, imp_w1, 384, imp_b1, scrB, GELU);
        dot_head_k<<<NB / 8, 256>>>(scrB, 384, imp_w2, imp_b2, out + (8 + i) * NB);
    }

    // discriminator (rows 12..15): img, eimg, txt, etxt
    const float* discfeats[4] = { img, eimg, txt, etxt };
    for (int i = 0; i < 4; i++) {
        launch_gemm(discfeats[i], nullptr, 768, 768, disc_w1, 256, disc_b1, scrC, GELU);
        launch_gemm(scrC, nullptr, 256, 256, disc_w2, 64, disc_b2, scrD, GELU);
        dot_head_k<<<NB / 8, 256>>>(scrD, 64, disc_w3, disc_b3, out + (12 + i) * NB);
    }

    // consistency original (row 6)
    launch_gemm(img, txt, 768, 1536, cons_w1, 768, cons_b1, scrA, GELU);
    launch_gemm(scrA, nullptr, 768, 768, cons_w2, 384, cons_b2, scrB, GELU);
    dot_head_k<<<NB / 8, 256>>>(scrB, 384, cons_w3, cons_b3, out + 6 * NB);

    // consistency enhanced (row 7)
    launch_gemm(eimg, etxt, 768, 1536, cons_w1, 768, cons_b1, scrA, GELU);
    launch_gemm(scrA, nullptr, 768, 768, cons_w2, 384, cons_b2, scrB, GELU);
    dot_head_k<<<NB / 8, 256>>>(scrB, 384, cons_w3, cons_b3, out + 7 * NB);

    // difficulty (row 16)
    launch_gemm(eimg, etxt, 768, 1536, diff_w1, 768, diff_b1, scrA, GELU);
    launch_gemm(scrA, nullptr, 768, 768, diff_w2, 384, diff_b2, scrB, GELU);
    dot_head_k<<<NB / 8, 256>>>(scrB, 384, diff_w3, diff_b3, out + 16 * NB);

    // overall (row 17)
    overall_k<<<NB / 256, 256>>>(out);
}

// round 4
// speedup vs baseline: 2.4389x; 2.4389x over previous
#include <cuda_runtime.h>
#include <cstdint>

#define NB 16384
#define HD 768

// ---------------- scratch (device globals; no allocs allowed) ----------------
__device__ float g_scrA[NB * 768];
__device__ float g_scrB[NB * 384];
__device__ float g_scrC[NB * 256];
__device__ float g_scrD[NB * 64];
__device__ float g_norm[2 * NB];
// transposed weights [N, K] K-major
__device__ float g_w_imp1[384 * 768];
__device__ float g_w_disc1[256 * 768];
__device__ float g_w_disc2[64 * 256];
__device__ float g_w_cons1[768 * 1536];
__device__ float g_w_cons2[384 * 768];
__device__ float g_w_diff1[768 * 1536];
__device__ float g_w_diff2[384 * 768];
__device__ float g_w_info1[256 * 768];
__device__ float g_w_info2[64 * 256];

__device__ __forceinline__ float sigf(float x) { return 1.0f / (1.0f + expf(-x)); }
__device__ __forceinline__ float geluf(float x) { return 0.5f * x * (1.0f + erff(x * 0.70710678118654752f)); }

__device__ __forceinline__ uint32_t smem_u32(const void* p) {
    uint32_t a;
    asm("{ .reg .u64 t; cvta.to.shared.u64 t, %1; cvt.u32.u64 %0, t; }" : "=r"(a) : "l"(p));
    return a;
}
__device__ __forceinline__ void mma8(float* d, const uint32_t* a, uint32_t b0, uint32_t b1) {
    asm volatile(
        "mma.sync.aligned.m16n8k8.row.col.f32.tf32.tf32.f32 "
        "{%0,%1,%2,%3}, {%4,%5,%6,%7}, {%8,%9}, {%0,%1,%2,%3};"
        : "+f"(d[0]), "+f"(d[1]), "+f"(d[2]), "+f"(d[3])
        : "r"(a[0]), "r"(a[1]), "r"(a[2]), "r"(a[3]), "r"(b0), "r"(b1));
}
#define LDSM4(r, addr) \
    asm volatile("ldmatrix.sync.aligned.m8n8.x4.shared.b16 {%0,%1,%2,%3}, [%4];" \
        : "=r"((r)[0]), "=r"((r)[1]), "=r"((r)[2]), "=r"((r)[3]) : "r"(addr))
#define CP_ASYNC16(dst, src) \
    asm volatile("cp.async.cg.shared.global [%0], [%1], 16;" :: "r"(dst), "l"(src))
#define CP_COMMIT() asm volatile("cp.async.commit_group;" ::: "memory")

__device__ __forceinline__ void split_tf32(uint32_t x, uint32_t& h, uint32_t& l) {
    h = x & 0xFFFFE000u;
    l = __float_as_uint(__uint_as_float(x) - __uint_as_float(h));
}

// ---------------- tf32 mma.sync GEMM: C = act(A @ Wt^T + bias) ----------------
// A: [NB, Khalf] fp32 row-major (two halves for concat). Wt: [N, Ktot] K-major.
// BM=128, BK=32, 256 threads, 8 warps (4 M x 2 N). P3 = 3xTF32 precise path.
template<int BN, bool P3>
__global__ void __launch_bounds__(256) gemm_mma(
    const float* __restrict__ A1, const float* __restrict__ A2,
    int Khalf, int Ktot, const float* __restrict__ Wt, int N,
    const float* __restrict__ bias, float* __restrict__ C, int act)
{
    constexpr int AW = 36;                     // padded row stride in floats
    constexpr int ABYTES = 128 * AW * 4;
    constexpr int BBYTES = BN * AW * 4;
    constexpr int STG = ABYTES + BBYTES;
    constexpr int NT = BN / 16;                // n-tiles per warp (warp spans BN/2 cols)

    extern __shared__ char smem[];
    const int t = threadIdx.x, lane = t & 31, wid = t >> 5;
    const int m0 = blockIdx.y * 128, n0 = blockIdx.x * BN;
    const int wm = (wid & 3) * 32;
    const int wn = (wid >> 2) * (BN / 2);

    const uint32_t sbase = smem_u32(smem);

    // ldmatrix lane addressing (A: rows wm.., B: rows wn..; both stride AW, cf-free)
    const int a_r = wm + (lane & 15);
    const int a_c = (lane >> 4) * 4;
    const uint32_t a_addr0 = sbase + (uint32_t)(a_r * AW + a_c) * 4;
    const int grp = lane >> 3;
    const int b_r = (lane & 7) + ((grp >= 2) ? 8 : 0);
    const int b_c = (grp & 1) * 4;
    const uint32_t b_addr0 = sbase + ABYTES + (uint32_t)((wn + b_r) * AW + b_c) * 4;

    float acc[2][NT][4];
#pragma unroll
    for (int i = 0; i < 2; i++)
#pragma unroll
        for (int j = 0; j < NT; j++)
#pragma unroll
            for (int q = 0; q < 4; q++) acc[i][j][q] = 0.0f;

    auto load_chunk = [&](int c) {
        const int b = c & 1;
        int kk = c * 32;
        const float* Ab = A1;
        if (kk >= Khalf) { Ab = A2; kk -= Khalf; }
        uint32_t sA = sbase + b * STG;
#pragma unroll
        for (int i = 0; i < 4; i++) {
            int idx = t + i * 256, r = idx >> 3, c4 = idx & 7;
            CP_ASYNC16(sA + (uint32_t)(r * AW + c4 * 4) * 4,
                       Ab + (size_t)(m0 + r) * Khalf + kk + c4 * 4);
        }
        uint32_t sB = sA + ABYTES;
#pragma unroll
        for (int i = 0; i < BN / 32; i++) {
            int idx = t + i * 256, r = idx >> 3, c4 = idx & 7;
            CP_ASYNC16(sB + (uint32_t)(r * AW + c4 * 4) * 4,
                       Wt + (size_t)(n0 + r) * Ktot + c * 32 + c4 * 4);
        }
        CP_COMMIT();
    };

    const int NC = Ktot >> 5;
    load_chunk(0);
    if (NC > 1) load_chunk(1);

    for (int c = 0; c < NC; c++) {
        if (c + 1 < NC) { asm volatile("cp.async.wait_group 1;" ::: "memory"); }
        else            { asm volatile("cp.async.wait_group 0;" ::: "memory"); }
        __syncthreads();

        const uint32_t aa = a_addr0 + (c & 1) * STG;
        const uint32_t bb = b_addr0 + (c & 1) * STG;
#pragma unroll
        for (int kk = 0; kk < 4; kk++) {
            uint32_t Ah[2][4], Al[2][4];
            LDSM4(Ah[0], aa + kk * 32);
            LDSM4(Ah[1], aa + 16 * AW * 4 + kk * 32);
            if (P3) {
#pragma unroll
                for (int mt = 0; mt < 2; mt++)
#pragma unroll
                    for (int q = 0; q < 4; q++) split_tf32(Ah[mt][q], Ah[mt][q], Al[mt][q]);
            }
#pragma unroll
            for (int np = 0; np < NT / 2; np++) {
                uint32_t B4[4];
                LDSM4(B4, bb + np * 16 * AW * 4 + kk * 32);
                if (!P3) {
#pragma unroll
                    for (int mt = 0; mt < 2; mt++) {
                        mma8(acc[mt][2 * np],     Ah[mt], B4[0], B4[1]);
                        mma8(acc[mt][2 * np + 1], Ah[mt], B4[2], B4[3]);
                    }
                } else {
                    uint32_t Bh[4], Bl[4];
#pragma unroll
                    for (int q = 0; q < 4; q++) split_tf32(B4[q], Bh[q], Bl[q]);
#pragma unroll
                    for (int mt = 0; mt < 2; mt++) {
                        mma8(acc[mt][2 * np],     Ah[mt], Bh[0], Bh[1]);
                        mma8(acc[mt][2 * np],     Ah[mt], Bl[0], Bl[1]);
                        mma8(acc[mt][2 * np],     Al[mt], Bh[0], Bh[1]);
                        mma8(acc[mt][2 * np + 1], Ah[mt], Bh[2], Bh[3]);
                        mma8(acc[mt][2 * np + 1], Ah[mt], Bl[2], Bl[3]);
                        mma8(acc[mt][2 * np + 1], Al[mt], Bh[2], Bh[3]);
                    }
                }
            }
        }
        __syncthreads();
        if (c + 2 < NC) load_chunk(c + 2);
    }

    // epilogue: bias + optional GELU, write float2 pairs
#pragma unroll
    for (int mt = 0; mt < 2; mt++) {
        int row = m0 + wm + mt * 16 + (lane >> 2);
#pragma unroll
        for (int nt = 0; nt < NT; nt++) {
            int col = n0 + wn + nt * 8 + (lane & 3) * 2;
            float b0v = bias[col], b1v = bias[col + 1];
            float x0 = acc[mt][nt][0] + b0v, x1 = acc[mt][nt][1] + b1v;
            float x2 = acc[mt][nt][2] + b0v, x3 = acc[mt][nt][3] + b1v;
            if (act) { x0 = geluf(x0); x1 = geluf(x1); x2 = geluf(x2); x3 = geluf(x3); }
            float2 v0 = make_float2(x0, x1), v1 = make_float2(x2, x3);
            *reinterpret_cast<float2*>(C + (size_t)row * N + col) = v0;
            *reinterpret_cast<float2*>(C + (size_t)(row + 8) * N + col) = v1;
        }
    }
}

// ---------------- weight transpose [K,N] -> [N,K] ----------------
__global__ void transpose_k(const float* __restrict__ s, float* __restrict__ d, int K, int N) {
    __shared__ float tile[32][33];
    int n = blockIdx.x * 32 + threadIdx.x;
    int k = blockIdx.y * 32 + threadIdx.y;
#pragma unroll
    for (int i = 0; i < 32; i += 8) tile[threadIdx.y + i][threadIdx.x] = s[(size_t)(k + i) * N + n];
    __syncthreads();
    int n2 = blockIdx.x * 32 + threadIdx.y;
    int k2 = blockIdx.y * 32 + threadIdx.x;
#pragma unroll
    for (int i = 0; i < 32; i += 8) d[(size_t)(n2 + i) * K + k2] = tile[threadIdx.x][threadIdx.y + i];
}

// ---------------- final dot head ----------------
__global__ void dot_head_k(const float* __restrict__ Hin, int K,
                           const float* __restrict__ w, const float* __restrict__ b,
                           float* __restrict__ outrow)
{
    int gw = (blockIdx.x * blockDim.x + threadIdx.x) >> 5;
    int lane = threadIdx.x & 31;
    if (gw >= NB) return;
    const float* row = Hin + (size_t)gw * K;
    float s = 0.f;
    for (int k = lane * 4; k < K; k += 128) {
        float4 v = *reinterpret_cast<const float4*>(row + k);
        float4 wv = *reinterpret_cast<const float4*>(w + k);
        s += v.x * wv.x + v.y * wv.y + v.z * wv.z + v.w * wv.w;
    }
#pragma unroll
    for (int o = 16; o; o >>= 1) s += __shfl_xor_sync(0xffffffffu, s, o);
    if (lane == 0) outrow[gw] = sigf(s + b[0]);
}

// ---------------- geometric quality (rows 0..3) + norms ----------------
__global__ void rowstats_k(const float* __restrict__ f0, const float* __restrict__ f1,
                           const float* __restrict__ f2, const float* __restrict__ f3,
                           float* __restrict__ out)
{
    int gw = (blockIdx.x * blockDim.x + threadIdx.x) >> 5;
    int lane = threadIdx.x & 31;
    if (gw >= 4 * NB) return;
    int feat = gw >> 14;
    int m = gw & (NB - 1);
    const float* f = (feat == 0 ? f0 : feat == 1 ? f1 : feat == 2 ? f2 : f3) + (size_t)m * HD;
    double sum = 0.0, ssq = 0.0;
    int cnt = 0;
    for (int k = lane * 4; k < HD; k += 128) {
        float4 v = *reinterpret_cast<const float4*>(f + k);
        sum += (double)v.x + v.y + v.z + v.w;
        ssq += (double)v.x * v.x + (double)v.y * v.y + (double)v.z * v.z + (double)v.w * v.w;
        cnt += (fabsf(v.x) > 0.01f) + (fabsf(v.y) > 0.01f) + (fabsf(v.z) > 0.01f) + (fabsf(v.w) > 0.01f);
    }
#pragma unroll
    for (int o = 16; o; o >>= 1) {
        sum += __shfl_xor_sync(0xffffffffu, sum, o);
        ssq += __shfl_xor_sync(0xffffffffu, ssq, o);
        cnt += __shfl_xor_sync(0xffffffffu, cnt, o);
    }
    if (lane == 0) {
        float n = (float)sqrt(ssq);
        float nq = sigf((n - 1.0f) * 2.0f);
        float sp = cnt * (1.0f / 768.0f);
        double var = (ssq - sum * sum / 768.0) / 767.0;
        if (var < 0.0) var = 0.0;
        float sq = sigf((float)sqrt(var) * 10.0f - 1.0f);
        out[feat * NB + m] = (nq + sp + sq) * (1.0f / 3.0f);
        if (feat < 2) g_norm[feat * NB + m] = n;
    }
}

// ---------------- information quality final ----------------
__global__ void info_final_k(const float* __restrict__ enc, int fi, float* __restrict__ outrow)
{
    int gw = (blockIdx.x * blockDim.x + threadIdx.x) >> 5;
    int lane = threadIdx.x & 31;
    if (gw >= NB) return;
    const float* e = enc + (size_t)gw * 64;
    float x0 = e[lane], x1 = e[lane + 32];
    int d0 = (int)rintf(sigf(x0) * 10.0f);
    int d1 = (int)rintf(sigf(x1) * 10.0f);
    float ent = 0.f;
#pragma unroll
    for (int b = 0; b < 11; b++) {
        int c = __popc(__ballot_sync(0xffffffffu, d0 == b)) +
                __popc(__ballot_sync(0xffffffffu, d1 == b));
        if (c > 0) {
            float p = c * (1.0f / 64.0f);
            ent -= p * logf(p + 1e-8f);
        }
    }
    if (lane == 0) {
        float eq = sigf(ent - 2.0f);
        float n = g_norm[fi * NB + gw];
        float cq = (n > 0.01f) ? (1.0f / 768.0f) : 0.0f;
        float t = n / fmaxf(n, 1e-12f);
        float dq = sigf(t * t - 0.5f);
        outrow[gw] = (eq + cq + dq) * (1.0f / 3.0f);
    }
}

__global__ void overall_k(float* __restrict__ out)
{
    int i = blockIdx.x * blockDim.x + threadIdx.x;
    if (i >= NB) return;
    float v = out[0 * NB + i] + out[1 * NB + i] + out[4 * NB + i] + out[5 * NB + i] +
              out[7 * NB + i] + 0.5f * (out[8 * NB + i] + out[9 * NB + i]);
    out[17 * NB + i] = v * (1.0f / 6.0f);
}

// ---------------- host ----------------
template<int BN, bool P3>
static void launch_gemm(const float* A1, const float* A2, int Khalf, int Ktot,
                        const float* Wt, int N, const float* bias, float* C, int act)
{
    int smemB = 2 * ((128 + BN) * 36 * 4);
    cudaFuncSetAttribute(gemm_mma<BN, P3>, cudaFuncAttributeMaxDynamicSharedMemorySize, smemB);
    dim3 g(N / BN, NB / 128);
    gemm_mma<BN, P3><<<g, 256, smemB>>>(A1, A2 ? A2 : A1, Khalf, Ktot, Wt, N, bias, C, act);
}
static void tr(const float* s, float* d, int K, int N) {
    dim3 b(32, 8), g(N / 32, K / 32);
    transpose_k<<<g, b>>>(s, d, K, N);
}

extern "C" void kernel_launch(void* const* d_in, const int* in_sizes, int n_in,
                              void* d_out, int out_size)
{
    const float* img  = (const float*)d_in[0];
    const float* txt  = (const float*)d_in[1];
    const float* eimg = (const float*)d_in[2];
    const float* etxt = (const float*)d_in[3];
    const float* info_w1 = (const float*)d_in[5];
    const float* info_b1 = (const float*)d_in[6];
    const float* info_w2 = (const float*)d_in[7];
    const float* info_b2 = (const float*)d_in[8];
    const float* imp_w1  = (const float*)d_in[9];
    const float* imp_b1  = (const float*)d_in[10];
    const float* imp_w2  = (const float*)d_in[11];
    const float* imp_b2  = (const float*)d_in[12];
    const float* disc_w1 = (const float*)d_in[13];
    const float* disc_b1 = (const float*)d_in[14];
    const float* disc_w2 = (const float*)d_in[15];
    const float* disc_b2 = (const float*)d_in[16];
    const float* disc_w3 = (const float*)d_in[17];
    const float* disc_b3 = (const float*)d_in[18];
    const float* cons_w1 = (const float*)d_in[19];
    const float* cons_b1 = (const float*)d_in[20];
    const float* cons_w2 = (const float*)d_in[21];
    const float* cons_b2 = (const float*)d_in[22];
    const float* cons_w3 = (const float*)d_in[23];
    const float* cons_b3 = (const float*)d_in[24];
    const float* diff_w1 = (const float*)d_in[25];
    const float* diff_b1 = (const float*)d_in[26];
    const float* diff_w2 = (const float*)d_in[27];
    const float* diff_b2 = (const float*)d_in[28];
    const float* diff_w3 = (const float*)d_in[29];
    const float* diff_b3 = (const float*)d_in[30];

    float* out = (float*)d_out;

    float *scrA, *scrB, *scrC, *scrD;
    float *w_imp1, *w_disc1, *w_disc2, *w_cons1, *w_cons2, *w_diff1, *w_diff2, *w_i1, *w_i2;
    cudaGetSymbolAddress((void**)&scrA, g_scrA);
    cudaGetSymbolAddress((void**)&scrB, g_scrB);
    cudaGetSymbolAddress((void**)&scrC, g_scrC);
    cudaGetSymbolAddress((void**)&scrD, g_scrD);
    cudaGetSymbolAddress((void**)&w_imp1, g_w_imp1);
    cudaGetSymbolAddress((void**)&w_disc1, g_w_disc1);
    cudaGetSymbolAddress((void**)&w_disc2, g_w_disc2);
    cudaGetSymbolAddress((void**)&w_cons1, g_w_cons1);
    cudaGetSymbolAddress((void**)&w_cons2, g_w_cons2);
    cudaGetSymbolAddress((void**)&w_diff1, g_w_diff1);
    cudaGetSymbolAddress((void**)&w_diff2, g_w_diff2);
    cudaGetSymbolAddress((void**)&w_i1, g_w_info1);
    cudaGetSymbolAddress((void**)&w_i2, g_w_info2);

    // weight transposes
    tr(imp_w1, w_imp1, 768, 384);
    tr(disc_w1, w_disc1, 768, 256);
    tr(disc_w2, w_disc2, 256, 64);
    tr(cons_w1, w_cons1, 1536, 768);
    tr(cons_w2, w_cons2, 768, 384);
    tr(diff_w1, w_diff1, 1536, 768);
    tr(diff_w2, w_diff2, 768, 384);
    tr(info_w1, w_i1, 768, 256);
    tr(info_w2, w_i2, 256, 64);

    // geometric (rows 0..3) + norms
    rowstats_k<<<(4 * NB) / 8, 256>>>(img, txt, eimg, etxt, out);

    // information (rows 4,5) — precise 3xTF32 path
    const float* infeats[2] = { img, txt };
    for (int i = 0; i < 2; i++) {
        launch_gemm<128, true>(infeats[i], nullptr, 768, 768, w_i1, 256, info_b1, scrC, 1);
        launch_gemm<64, true>(scrC, nullptr, 256, 256, w_i2, 64, info_b2, scrD, 0);
        info_final_k<<<NB / 8, 256>>>(scrD, i, out + (4 + i) * NB);
    }

    // importance (rows 8..11)
    const float* impfeats[4] = { img, txt, eimg, etxt };
    for (int i = 0; i < 4; i++) {
        launch_gemm<128, false>(impfeats[i], nullptr, 768, 768, w_imp1, 384, imp_b1, scrB, 1);
        dot_head_k<<<NB / 8, 256>>>(scrB, 384, imp_w2, imp_b2, out + (8 + i) * NB);
    }

    // discriminator (rows 12..15): img, eimg, txt, etxt
    const float* discfeats[4] = { img, eimg, txt, etxt };
    for (int i = 0; i < 4; i++) {
        launch_gemm<128, false>(discfeats[i], nullptr, 768, 768, w_disc1, 256, disc_b1, scrC, 1);
        launch_gemm<64, false>(scrC, nullptr, 256, 256, w_disc2, 64, disc_b2, scrD, 1);
        dot_head_k<<<NB / 8, 256>>>(scrD, 64, disc_w3, disc_b3, out + (12 + i) * NB);
    }

    // consistency original (row 6)
    launch_gemm<128, false>(img, txt, 768, 1536, w_cons1, 768, cons_b1, scrA, 1);
    launch_gemm<128, false>(scrA, nullptr, 768, 768, w_cons2, 384, cons_b2, scrB, 1);
    dot_head_k<<<NB / 8, 256>>>(scrB, 384, cons_w3, cons_b3, out + 6 * NB);

    // consistency enhanced (row 7)
    launch_gemm<128, false>(eimg, etxt, 768, 1536, w_cons1, 768, cons_b1, scrA, 1);
    launch_gemm<128, false>(scrA, nullptr, 768, 768, w_cons2, 384, cons_b2, scrB, 1);
    dot_head_k<<<NB / 8, 256>>>(scrB, 384, cons_w3, cons_b3, out + 7 * NB);

    // difficulty (row 16)
    launch_gemm<128, false>(eimg, etxt, 768, 1536, w_diff1, 768, diff_b1, scrA, 1);
    launch_gemm<128, false>(scrA, nullptr, 768, 768, w_diff2, 384, diff_b2, scrB, 1);
    dot_head_k<<<NB / 8, 256>>>(scrB, 384, diff_w3, diff_b3, out + 16 * NB);

    // overall (row 17)
    overall_k<<<NB / 256, 256>>>(out);
}

// round 5
// speedup vs baseline: 2.6275x; 1.0773x over previous
#include <cuda_runtime.h>
#include <cstdint>

#define NB 16384
#define HD 768

// ---------------- scratch (device globals; no allocs allowed) ----------------
__device__ float g_scrA[2 * NB * 768];   // cons1 batched output
__device__ float g_scrB[4 * NB * 384];   // imp1 / cons2 / diff2 outputs
__device__ float g_scrC[4 * NB * 256];   // disc1 / info1 outputs
__device__ float g_scrD[4 * NB * 64];    // disc2 / info2 outputs
__device__ float g_norm[2 * NB];
// transposed weights [N, K] K-major
__device__ float g_w_imp1[384 * 768];
__device__ float g_w_disc1[256 * 768];
__device__ float g_w_disc2[64 * 256];
__device__ float g_w_cons1[768 * 1536];
__device__ float g_w_cons2[384 * 768];
__device__ float g_w_diff1[768 * 1536];
__device__ float g_w_diff2[384 * 768];
__device__ float g_w_info1[256 * 768];
__device__ float g_w_info2[64 * 256];

__device__ __forceinline__ float sigf(float x) { return 1.0f / (1.0f + expf(-x)); }
__device__ __forceinline__ float geluf(float x) { return 0.5f * x * (1.0f + erff(x * 0.70710678118654752f)); }

__device__ __forceinline__ uint32_t smem_u32(const void* p) {
    uint32_t a;
    asm("{ .reg .u64 t; cvta.to.shared.u64 t, %1; cvt.u32.u64 %0, t; }" : "=r"(a) : "l"(p));
    return a;
}
__device__ __forceinline__ void mma8(float* d, const uint32_t* a, uint32_t b0, uint32_t b1) {
    asm volatile(
        "mma.sync.aligned.m16n8k8.row.col.f32.tf32.tf32.f32 "
        "{%0,%1,%2,%3}, {%4,%5,%6,%7}, {%8,%9}, {%0,%1,%2,%3};"
        : "+f"(d[0]), "+f"(d[1]), "+f"(d[2]), "+f"(d[3])
        : "r"(a[0]), "r"(a[1]), "r"(a[2]), "r"(a[3]), "r"(b0), "r"(b1));
}
#define LDSM4(r, addr) \
    asm volatile("ldmatrix.sync.aligned.m8n8.x4.shared.b16 {%0,%1,%2,%3}, [%4];" \
        : "=r"((r)[0]), "=r"((r)[1]), "=r"((r)[2]), "=r"((r)[3]) : "r"(addr))
#define CP_ASYNC16(dst, src) \
    asm volatile("cp.async.cg.shared.global [%0], [%1], 16;" :: "r"(dst), "l"(src))
#define CP_COMMIT() asm volatile("cp.async.commit_group;" ::: "memory")

__device__ __forceinline__ void split_tf32(uint32_t x, uint32_t& h, uint32_t& l) {
    h = x & 0xFFFFE000u;
    l = __float_as_uint(__uint_as_float(x) - __uint_as_float(h));
}

struct APtrs { const float* p[4]; };

// ---------------- tf32 mma.sync GEMM (batched over M): C = act(A @ Wt^T + bias) ----------------
// Each batch is NB rows (128 CTAs in y per batch). Concat mode when Khalf < Ktot:
// batch b uses pair (p[2b], p[2b+1]); else p[b]. Wt: [N, Ktot] K-major.
// BM=128, BK=32, 3-stage cp.async pipeline, one __syncthreads per chunk.
template<int BN, bool P3>
__global__ void __launch_bounds__(256, 2) gemm_mma(
    APtrs A, int Khalf, int Ktot, const float* __restrict__ Wt, int N,
    const float* __restrict__ bias, float* __restrict__ C, int act)
{
    constexpr int AW = 36;
    constexpr int ABYTES = 128 * AW * 4;
    constexpr int BBYTES = BN * AW * 4;
    constexpr int STG = ABYTES + BBYTES;
    constexpr int NT = BN / 16;

    extern __shared__ char smem[];
    const int t = threadIdx.x, lane = t & 31, wid = t >> 5;
    const int batch = blockIdx.y >> 7;
    const int m0 = (blockIdx.y & 127) * 128;
    const int n0 = blockIdx.x * BN;
    const int wm = (wid & 3) * 32;
    const int wn = (wid >> 2) * (BN / 2);

    const float *A1, *A2;
    if (Khalf < Ktot) { A1 = A.p[2 * batch]; A2 = A.p[2 * batch + 1]; }
    else              { A1 = A.p[batch];     A2 = A1; }
    C += (size_t)batch * NB * N;

    const uint32_t sbase = smem_u32(smem);

    const int a_r = wm + (lane & 15);
    const int a_c = (lane >> 4) * 4;
    const uint32_t a_addr0 = sbase + (uint32_t)(a_r * AW + a_c) * 4;
    const int grp = lane >> 3;
    const int b_r = (lane & 7) + ((grp >= 2) ? 8 : 0);
    const int b_c = (grp & 1) * 4;
    const uint32_t b_addr0 = sbase + ABYTES + (uint32_t)((wn + b_r) * AW + b_c) * 4;

    float acc[2][NT][4];
#pragma unroll
    for (int i = 0; i < 2; i++)
#pragma unroll
        for (int j = 0; j < NT; j++)
#pragma unroll
            for (int q = 0; q < 4; q++) acc[i][j][q] = 0.0f;

    auto load_chunk = [&](int c) {
        const int stg = c % 3;
        int kk = c * 32;
        const float* Ab = A1;
        if (kk >= Khalf) { Ab = A2; kk -= Khalf; }
        uint32_t sA = sbase + stg * STG;
#pragma unroll
        for (int i = 0; i < 4; i++) {
            int idx = t + i * 256, r = idx >> 3, c4 = idx & 7;
            CP_ASYNC16(sA + (uint32_t)(r * AW + c4 * 4) * 4,
                       Ab + (size_t)(m0 + r) * Khalf + kk + c4 * 4);
        }
        uint32_t sB = sA + ABYTES;
#pragma unroll
        for (int i = 0; i < BN / 32; i++) {
            int idx = t + i * 256, r = idx >> 3, c4 = idx & 7;
            CP_ASYNC16(sB + (uint32_t)(r * AW + c4 * 4) * 4,
                       Wt + (size_t)(n0 + r) * Ktot + c * 32 + c4 * 4);
        }
        CP_COMMIT();
    };

    const int NC = Ktot >> 5;
    load_chunk(0);
    if (NC > 1) load_chunk(1);

    for (int c = 0; c < NC; c++) {
        // my chunk-c group arrived (pending <= the c+1 group, if any)
        if (c + 1 < NC) { asm volatile("cp.async.wait_group 1;" ::: "memory"); }
        else            { asm volatile("cp.async.wait_group 0;" ::: "memory"); }
        // barrier: (a) makes everyone's chunk-c data visible, (b) everyone done computing c-1,
        // so stage (c+2)%3 == (c-1)%3 is free to overwrite.
        __syncthreads();
        if (c + 2 < NC) load_chunk(c + 2);

        const uint32_t aa = a_addr0 + (c % 3) * STG;
        const uint32_t bb = b_addr0 + (c % 3) * STG;
#pragma unroll
        for (int kk = 0; kk < 4; kk++) {
            uint32_t Ah[2][4], Al[2][4];
            LDSM4(Ah[0], aa + kk * 32);
            LDSM4(Ah[1], aa + 16 * AW * 4 + kk * 32);
            if (P3) {
#pragma unroll
                for (int mt = 0; mt < 2; mt++)
#pragma unroll
                    for (int q = 0; q < 4; q++) split_tf32(Ah[mt][q], Ah[mt][q], Al[mt][q]);
            }
#pragma unroll
            for (int np = 0; np < NT / 2; np++) {
                uint32_t B4[4];
                LDSM4(B4, bb + np * 16 * AW * 4 + kk * 32);
                if (!P3) {
#pragma unroll
                    for (int mt = 0; mt < 2; mt++) {
                        mma8(acc[mt][2 * np],     Ah[mt], B4[0], B4[1]);
                        mma8(acc[mt][2 * np + 1], Ah[mt], B4[2], B4[3]);
                    }
                } else {
                    uint32_t Bh[4], Bl[4];
#pragma unroll
                    for (int q = 0; q < 4; q++) split_tf32(B4[q], Bh[q], Bl[q]);
#pragma unroll
                    for (int mt = 0; mt < 2; mt++) {
                        mma8(acc[mt][2 * np],     Ah[mt], Bh[0], Bh[1]);
                        mma8(acc[mt][2 * np],     Ah[mt], Bl[0], Bl[1]);
                        mma8(acc[mt][2 * np],     Al[mt], Bh[0], Bh[1]);
                        mma8(acc[mt][2 * np + 1], Ah[mt], Bh[2], Bh[3]);
                        mma8(acc[mt][2 * np + 1], Ah[mt], Bl[2], Bl[3]);
                        mma8(acc[mt][2 * np + 1], Al[mt], Bh[2], Bh[3]);
                    }
                }
            }
        }
    }

#pragma unroll
    for (int mt = 0; mt < 2; mt++) {
        int row = m0 + wm + mt * 16 + (lane >> 2);
#pragma unroll
        for (int nt = 0; nt < NT; nt++) {
            int col = n0 + wn + nt * 8 + (lane & 3) * 2;
            float b0v = bias[col], b1v = bias[col + 1];
            float x0 = acc[mt][nt][0] + b0v, x1 = acc[mt][nt][1] + b1v;
            float x2 = acc[mt][nt][2] + b0v, x3 = acc[mt][nt][3] + b1v;
            if (act) { x0 = geluf(x0); x1 = geluf(x1); x2 = geluf(x2); x3 = geluf(x3); }
            *reinterpret_cast<float2*>(C + (size_t)row * N + col)       = make_float2(x0, x1);
            *reinterpret_cast<float2*>(C + (size_t)(row + 8) * N + col) = make_float2(x2, x3);
        }
    }
}

// ---------------- weight transpose [K,N] -> [N,K] ----------------
__global__ void transpose_k(const float* __restrict__ s, float* __restrict__ d, int K, int N) {
    __shared__ float tile[32][33];
    int n = blockIdx.x * 32 + threadIdx.x;
    int k = blockIdx.y * 32 + threadIdx.y;
#pragma unroll
    for (int i = 0; i < 32; i += 8) tile[threadIdx.y + i][threadIdx.x] = s[(size_t)(k + i) * N + n];
    __syncthreads();
    int n2 = blockIdx.x * 32 + threadIdx.y;
    int k2 = blockIdx.y * 32 + threadIdx.x;
#pragma unroll
    for (int i = 0; i < 32; i += 8) d[(size_t)(n2 + i) * K + k2] = tile[threadIdx.x][threadIdx.y + i];
}

// ---------------- final dot head (batched): out[gw] = sigmoid(H[gw,:].w + b) ----------------
__global__ void dot_head_k(const float* __restrict__ Hin, int K, int rows,
                           const float* __restrict__ w, const float* __restrict__ b,
                           float* __restrict__ outrow)
{
    int gw = (blockIdx.x * blockDim.x + threadIdx.x) >> 5;
    int lane = threadIdx.x & 31;
    if (gw >= rows) return;
    const float* row = Hin + (size_t)gw * K;
    float s = 0.f;
    for (int k = lane * 4; k < K; k += 128) {
        float4 v = *reinterpret_cast<const float4*>(row + k);
        float4 wv = *reinterpret_cast<const float4*>(w + k);
        s += v.x * wv.x + v.y * wv.y + v.z * wv.z + v.w * wv.w;
    }
#pragma unroll
    for (int o = 16; o; o >>= 1) s += __shfl_xor_sync(0xffffffffu, s, o);
    if (lane == 0) outrow[gw] = sigf(s + b[0]);
}

// ---------------- geometric quality (rows 0..3) + norms ----------------
__global__ void rowstats_k(const float* __restrict__ f0, const float* __restrict__ f1,
                           const float* __restrict__ f2, const float* __restrict__ f3,
                           float* __restrict__ out)
{
    int gw = (blockIdx.x * blockDim.x + threadIdx.x) >> 5;
    int lane = threadIdx.x & 31;
    if (gw >= 4 * NB) return;
    int feat = gw >> 14;
    int m = gw & (NB - 1);
    const float* f = (feat == 0 ? f0 : feat == 1 ? f1 : feat == 2 ? f2 : f3) + (size_t)m * HD;
    double sum = 0.0, ssq = 0.0;
    int cnt = 0;
    for (int k = lane * 4; k < HD; k += 128) {
        float4 v = *reinterpret_cast<const float4*>(f + k);
        sum += (double)v.x + v.y + v.z + v.w;
        ssq += (double)v.x * v.x + (double)v.y * v.y + (double)v.z * v.z + (double)v.w * v.w;
        cnt += (fabsf(v.x) > 0.01f) + (fabsf(v.y) > 0.01f) + (fabsf(v.z) > 0.01f) + (fabsf(v.w) > 0.01f);
    }
#pragma unroll
    for (int o = 16; o; o >>= 1) {
        sum += __shfl_xor_sync(0xffffffffu, sum, o);
        ssq += __shfl_xor_sync(0xffffffffu, ssq, o);
        cnt += __shfl_xor_sync(0xffffffffu, cnt, o);
    }
    if (lane == 0) {
        float n = (float)sqrt(ssq);
        float nq = sigf((n - 1.0f) * 2.0f);
        float sp = cnt * (1.0f / 768.0f);
        double var = (ssq - sum * sum / 768.0) / 767.0;
        if (var < 0.0) var = 0.0;
        float sq = sigf((float)sqrt(var) * 10.0f - 1.0f);
        out[feat * NB + m] = (nq + sp + sq) * (1.0f / 3.0f);
        if (feat < 2) g_norm[feat * NB + m] = n;
    }
}

// ---------------- information quality final (batched: 2*NB rows) ----------------
__global__ void info_final_k(const float* __restrict__ enc, float* __restrict__ outrow)
{
    int gw = (blockIdx.x * blockDim.x + threadIdx.x) >> 5;
    int lane = threadIdx.x & 31;
    if (gw >= 2 * NB) return;
    const float* e = enc + (size_t)gw * 64;
    float x0 = e[lane], x1 = e[lane + 32];
    int d0 = (int)rintf(sigf(x0) * 10.0f);
    int d1 = (int)rintf(sigf(x1) * 10.0f);
    float ent = 0.f;
#pragma unroll
    for (int b = 0; b < 11; b++) {
        int c = __popc(__ballot_sync(0xffffffffu, d0 == b)) +
                __popc(__ballot_sync(0xffffffffu, d1 == b));
        if (c > 0) {
            float p = c * (1.0f / 64.0f);
            ent -= p * logf(p + 1e-8f);
        }
    }
    if (lane == 0) {
        float eq = sigf(ent - 2.0f);
        float n = g_norm[gw];   // gw = fi*NB + m, matching g_norm layout
        float cq = (n > 0.01f) ? (1.0f / 768.0f) : 0.0f;
        float t = n / fmaxf(n, 1e-12f);
        float dq = sigf(t * t - 0.5f);
        outrow[gw] = (eq + cq + dq) * (1.0f / 3.0f);
    }
}

__global__ void overall_k(float* __restrict__ out)
{
    int i = blockIdx.x * blockDim.x + threadIdx.x;
    if (i >= NB) return;
    float v = out[0 * NB + i] + out[1 * NB + i] + out[4 * NB + i] + out[5 * NB + i] +
              out[7 * NB + i] + 0.5f * (out[8 * NB + i] + out[9 * NB + i]);
    out[17 * NB + i] = v * (1.0f / 6.0f);
}

// ---------------- host ----------------
template<int BN, bool P3>
static void launch_gemm(APtrs A, int nb, int Khalf, int Ktot,
                        const float* Wt, int N, const float* bias, float* C, int act)
{
    int smemB = 3 * (128 + BN) * 36 * 4;
    cudaFuncSetAttribute(gemm_mma<BN, P3>, cudaFuncAttributeMaxDynamicSharedMemorySize, smemB);
    dim3 g(N / BN, nb * 128);
    gemm_mma<BN, P3><<<g, 256, smemB>>>(A, Khalf, Ktot, Wt, N, bias, C, act);
}
static void tr(const float* s, float* d, int K, int N) {
    dim3 b(32, 8), g(N / 32, K / 32);
    transpose_k<<<g, b>>>(s, d, K, N);
}

extern "C" void kernel_launch(void* const* d_in, const int* in_sizes, int n_in,
                              void* d_out, int out_size)
{
    const float* img  = (const float*)d_in[0];
    const float* txt  = (const float*)d_in[1];
    const float* eimg = (const float*)d_in[2];
    const float* etxt = (const float*)d_in[3];
    const float* info_w1 = (const float*)d_in[5];
    const float* info_b1 = (const float*)d_in[6];
    const float* info_w2 = (const float*)d_in[7];
    const float* info_b2 = (const float*)d_in[8];
    const float* imp_w1  = (const float*)d_in[9];
    const float* imp_b1  = (const float*)d_in[10];
    const float* imp_w2  = (const float*)d_in[11];
    const float* imp_b2  = (const float*)d_in[12];
    const float* disc_w1 = (const float*)d_in[13];
    const float* disc_b1 = (const float*)d_in[14];
    const float* disc_w2 = (const float*)d_in[15];
    const float* disc_b2 = (const float*)d_in[16];
    const float* disc_w3 = (const float*)d_in[17];
    const float* disc_b3 = (const float*)d_in[18];
    const float* cons_w1 = (const float*)d_in[19];
    const float* cons_b1 = (const float*)d_in[20];
    const float* cons_w2 = (const float*)d_in[21];
    const float* cons_b2 = (const float*)d_in[22];
    const float* cons_w3 = (const float*)d_in[23];
    const float* cons_b3 = (const float*)d_in[24];
    const float* diff_w1 = (const float*)d_in[25];
    const float* diff_b1 = (const float*)d_in[26];
    const float* diff_w2 = (const float*)d_in[27];
    const float* diff_b2 = (const float*)d_in[28];
    const float* diff_w3 = (const float*)d_in[29];
    const float* diff_b3 = (const float*)d_in[30];

    float* out = (float*)d_out;

    float *scrA, *scrB, *scrC, *scrD;
    float *w_imp1, *w_disc1, *w_disc2, *w_cons1, *w_cons2, *w_diff1, *w_diff2, *w_i1, *w_i2;
    cudaGetSymbolAddress((void**)&scrA, g_scrA);
    cudaGetSymbolAddress((void**)&scrB, g_scrB);
    cudaGetSymbolAddress((void**)&scrC, g_scrC);
    cudaGetSymbolAddress((void**)&scrD, g_scrD);
    cudaGetSymbolAddress((void**)&w_imp1, g_w_imp1);
    cudaGetSymbolAddress((void**)&w_disc1, g_w_disc1);
    cudaGetSymbolAddress((void**)&w_disc2, g_w_disc2);
    cudaGetSymbolAddress((void**)&w_cons1, g_w_cons1);
    cudaGetSymbolAddress((void**)&w_cons2, g_w_cons2);
    cudaGetSymbolAddress((void**)&w_diff1, g_w_diff1);
    cudaGetSymbolAddress((void**)&w_diff2, g_w_diff2);
    cudaGetSymbolAddress((void**)&w_i1, g_w_info1);
    cudaGetSymbolAddress((void**)&w_i2, g_w_info2);

    // weight transposes
    tr(imp_w1, w_imp1, 768, 384);
    tr(disc_w1, w_disc1, 768, 256);
    tr(disc_w2, w_disc2, 256, 64);
    tr(cons_w1, w_cons1, 1536, 768);
    tr(cons_w2, w_cons2, 768, 384);
    tr(diff_w1, w_diff1, 1536, 768);
    tr(diff_w2, w_diff2, 768, 384);
    tr(info_w1, w_i1, 768, 256);
    tr(info_w2, w_i2, 256, 64);

    // geometric (rows 0..3) + norms
    rowstats_k<<<(4 * NB) / 8, 256>>>(img, txt, eimg, etxt, out);

    // information (rows 4,5) — batched 2, precise 3xTF32
    {
        APtrs a = {{ img, txt, nullptr, nullptr }};
        launch_gemm<128, true>(a, 2, 768, 768, w_i1, 256, info_b1, scrC, 1);
        APtrs a2 = {{ scrC, scrC + (size_t)NB * 256, nullptr, nullptr }};
        launch_gemm<64, true>(a2, 2, 256, 256, w_i2, 64, info_b2, scrD, 0);
        info_final_k<<<(2 * NB) / 8, 256>>>(scrD, out + 4 * NB);
    }

    // importance (rows 8..11) — batched 4: img, txt, eimg, etxt
    {
        APtrs a = {{ img, txt, eimg, etxt }};
        launch_gemm<128, false>(a, 4, 768, 768, w_imp1, 384, imp_b1, scrB, 1);
        dot_head_k<<<(4 * NB) / 8, 256>>>(scrB, 384, 4 * NB, imp_w2, imp_b2, out + 8 * NB);
    }

    // discriminator (rows 12..15) — batched 4: img, eimg, txt, etxt
    {
        APtrs a = {{ img, eimg, txt, etxt }};
        launch_gemm<128, false>(a, 4, 768, 768, w_disc1, 256, disc_b1, scrC, 1);
        APtrs a2 = {{ scrC, scrC + (size_t)NB * 256, scrC + (size_t)2 * NB * 256, scrC + (size_t)3 * NB * 256 }};
        launch_gemm<64, false>(a2, 4, 256, 256, w_disc2, 64, disc_b2, scrD, 1);
        dot_head_k<<<(4 * NB) / 8, 256>>>(scrD, 64, 4 * NB, disc_w3, disc_b3, out + 12 * NB);
    }

    // consistency (rows 6,7) — batched 2 concat pairs
    {
        APtrs a = {{ img, txt, eimg, etxt }};   // pairs: (img,txt), (eimg,etxt)
        launch_gemm<128, false>(a, 2, 768, 1536, w_cons1, 768, cons_b1, scrA, 1);
        APtrs a2 = {{ scrA, scrA + (size_t)NB * 768, nullptr, nullptr }};
        launch_gemm<128, false>(a2, 2, 768, 768, w_cons2, 384, cons_b2, scrB, 1);
        dot_head_k<<<(2 * NB) / 8, 256>>>(scrB, 384, 2 * NB, cons_w3, cons_b3, out + 6 * NB);
    }

    // difficulty (row 16) — single concat pair
    {
        APtrs a = {{ eimg, etxt, nullptr, nullptr }};
        launch_gemm<128, false>(a, 1, 768, 1536, w_diff1, 768, diff_b1, scrA, 1);
        APtrs a2 = {{ scrA, nullptr, nullptr, nullptr }};
        launch_gemm<128, false>(a2, 1, 768, 768, w_diff2, 384, diff_b2, scrB, 1);
        dot_head_k<<<NB / 8, 256>>>(scrB, 384, NB, diff_w3, diff_b3, out + 16 * NB);
    }

    // overall (row 17)
    overall_k<<<NB / 256, 256>>>(out);
}

// round 6
// speedup vs baseline: 3.3514x; 1.2755x over previous
#include <cuda_runtime.h>
#include <cuda_bf16.h>
#include <cstdint>

#define NB 16384
#define HD 768

// ---------------- scratch (device globals; no allocs allowed) ----------------
__device__ __nv_bfloat16 g_featbf[4 * NB * 768];     // bf16 copies of the 4 features
__device__ __nv_bfloat16 g_scrAbf[2 * NB * 768];     // cons1 / diff1 outputs (bf16)
__device__ __nv_bfloat16 g_scrCbf[4 * NB * 256];     // disc1 outputs (bf16)
__device__ float g_scrB[4 * NB * 384];               // imp1 / cons2 / diff2 outputs (fp32)
__device__ float g_scrC[2 * NB * 256];               // info1 outputs (fp32)
__device__ float g_scrD[4 * NB * 64];                // disc2 / info2 outputs (fp32)
__device__ float g_norm[2 * NB];
// bf16 transposed weights [N, K] K-major
__device__ __nv_bfloat16 g_w_imp1[384 * 768];
__device__ __nv_bfloat16 g_w_disc1[256 * 768];
__device__ __nv_bfloat16 g_w_disc2[64 * 256];
__device__ __nv_bfloat16 g_w_cons1[768 * 1536];
__device__ __nv_bfloat16 g_w_cons2[384 * 768];
__device__ __nv_bfloat16 g_w_diff1[768 * 1536];
__device__ __nv_bfloat16 g_w_diff2[384 * 768];
// fp32 transposed weights for the precise info path
__device__ float g_w_info1[256 * 768];
__device__ float g_w_info2[64 * 256];

__device__ __forceinline__ float sigf(float x) { return 1.0f / (1.0f + expf(-x)); }
__device__ __forceinline__ float geluf(float x) { return 0.5f * x * (1.0f + erff(x * 0.70710678118654752f)); }

__device__ __forceinline__ uint32_t smem_u32(const void* p) {
    uint32_t a;
    asm("{ .reg .u64 t; cvta.to.shared.u64 t, %1; cvt.u32.u64 %0, t; }" : "=r"(a) : "l"(p));
    return a;
}
__device__ __forceinline__ void mma_tf(float* d, const uint32_t* a, uint32_t b0, uint32_t b1) {
    asm volatile(
        "mma.sync.aligned.m16n8k8.row.col.f32.tf32.tf32.f32 "
        "{%0,%1,%2,%3}, {%4,%5,%6,%7}, {%8,%9}, {%0,%1,%2,%3};"
        : "+f"(d[0]), "+f"(d[1]), "+f"(d[2]), "+f"(d[3])
        : "r"(a[0]), "r"(a[1]), "r"(a[2]), "r"(a[3]), "r"(b0), "r"(b1));
}
__device__ __forceinline__ void mma_bf(float* d, const uint32_t* a, uint32_t b0, uint32_t b1) {
    asm volatile(
        "mma.sync.aligned.m16n8k16.row.col.f32.bf16.bf16.f32 "
        "{%0,%1,%2,%3}, {%4,%5,%6,%7}, {%8,%9}, {%0,%1,%2,%3};"
        : "+f"(d[0]), "+f"(d[1]), "+f"(d[2]), "+f"(d[3])
        : "r"(a[0]), "r"(a[1]), "r"(a[2]), "r"(a[3]), "r"(b0), "r"(b1));
}
#define LDSM4(r, addr) \
    asm volatile("ldmatrix.sync.aligned.m8n8.x4.shared.b16 {%0,%1,%2,%3}, [%4];" \
        : "=r"((r)[0]), "=r"((r)[1]), "=r"((r)[2]), "=r"((r)[3]) : "r"(addr))
#define CP_ASYNC16(dst, src) \
    asm volatile("cp.async.cg.shared.global [%0], [%1], 16;" :: "r"(dst), "l"(src))
#define CP_COMMIT() asm volatile("cp.async.commit_group;" ::: "memory")

__device__ __forceinline__ void split_tf32(uint32_t x, uint32_t& h, uint32_t& l) {
    h = x & 0xFFFFE000u;
    l = __float_as_uint(__uint_as_float(x) - __uint_as_float(h));
}

struct APtrs  { const float* p[4]; };
struct APtrsB { const __nv_bfloat16* p[4]; };

// ================= bf16 GEMM: C = act(A @ Wt^T + bias), batched over M =================
// A: bf16 [NB, Khalf] per batch (concat mode when Khalf<Ktot uses pairs).
// Wt: bf16 [N, Ktot]. BM=128, BK=32, 3-stage cp.async, 8 warps (4M x 2N).
template<int BN, bool OUTBF>
__global__ void __launch_bounds__(256, 2) gemm_bf16(
    APtrsB A, int Khalf, int Ktot, const __nv_bfloat16* __restrict__ Wt, int N,
    const float* __restrict__ bias, void* __restrict__ Cv, int act)
{
    constexpr int AW = 40;                 // row stride in bf16 elems (80B, cf-free for ldmatrix)
    constexpr int ABYTES = 128 * AW * 2;
    constexpr int BBYTES = BN * AW * 2;
    constexpr int STG = ABYTES + BBYTES;
    constexpr int NT = BN / 16;

    extern __shared__ char smem[];
    const int t = threadIdx.x, lane = t & 31, wid = t >> 5;
    const int batch = blockIdx.y >> 7;
    const int m0 = (blockIdx.y & 127) * 128;
    const int n0 = blockIdx.x * BN;
    const int wm = (wid & 3) * 32;
    const int wn = (wid >> 2) * (BN / 2);

    const __nv_bfloat16 *A1, *A2;
    if (Khalf < Ktot) { A1 = A.p[2 * batch]; A2 = A.p[2 * batch + 1]; }
    else              { A1 = A.p[batch];     A2 = A1; }

    const uint32_t sbase = smem_u32(smem);

    // ldmatrix lane addressing
    const uint32_t a_addr0 = sbase + (uint32_t)((wm + (lane & 15)) * AW * 2 + (lane >> 4) * 16);
    const int grp = lane >> 3;
    const int b_r = (lane & 7) + ((grp >= 2) ? 8 : 0);
    const uint32_t b_addr0 = sbase + ABYTES + (uint32_t)((wn + b_r) * AW * 2 + (grp & 1) * 16);

    float acc[2][NT][4];
#pragma unroll
    for (int i = 0; i < 2; i++)
#pragma unroll
        for (int j = 0; j < NT; j++)
#pragma unroll
            for (int q = 0; q < 4; q++) acc[i][j][q] = 0.0f;

    auto load_chunk = [&](int c) {
        const int stg = c % 3;
        int kk = c * 32;
        const __nv_bfloat16* Ab = A1;
        if (kk >= Khalf) { Ab = A2; kk -= Khalf; }
        uint32_t sA = sbase + stg * STG;
        // A tile: 128 rows x 32 bf16 = 512 x 16B
#pragma unroll
        for (int i = 0; i < 2; i++) {
            int idx = t + i * 256, r = idx >> 2, c8 = idx & 3;
            CP_ASYNC16(sA + (uint32_t)(r * AW * 2 + c8 * 16),
                       Ab + (size_t)(m0 + r) * Khalf + kk + c8 * 8);
        }
        uint32_t sB = sA + ABYTES;
#pragma unroll
        for (int i = 0; i < BN / 64; i++) {
            int idx = t + i * 256, r = idx >> 2, c8 = idx & 3;
            CP_ASYNC16(sB + (uint32_t)(r * AW * 2 + c8 * 16),
                       Wt + (size_t)(n0 + r) * Ktot + c * 32 + c8 * 8);
        }
        CP_COMMIT();
    };

    const int NC = Ktot >> 5;
    load_chunk(0);
    if (NC > 1) load_chunk(1);

    for (int c = 0; c < NC; c++) {
        if (c + 1 < NC) { asm volatile("cp.async.wait_group 1;" ::: "memory"); }
        else            { asm volatile("cp.async.wait_group 0;" ::: "memory"); }
        __syncthreads();
        if (c + 2 < NC) load_chunk(c + 2);

        const uint32_t aa = a_addr0 + (c % 3) * STG;
        const uint32_t bb = b_addr0 + (c % 3) * STG;
#pragma unroll
        for (int kk = 0; kk < 2; kk++) {      // two k16 steps per 32-chunk
            uint32_t Af[2][4];
            LDSM4(Af[0], aa + kk * 32);
            LDSM4(Af[1], aa + 16 * AW * 2 + kk * 32);
#pragma unroll
            for (int np = 0; np < NT / 2; np++) {
                uint32_t B4[4];
                LDSM4(B4, bb + np * 16 * AW * 2 + kk * 32);
#pragma unroll
                for (int mt = 0; mt < 2; mt++) {
                    mma_bf(acc[mt][2 * np],     Af[mt], B4[0], B4[1]);
                    mma_bf(acc[mt][2 * np + 1], Af[mt], B4[2], B4[3]);
                }
            }
        }
    }

#pragma unroll
    for (int mt = 0; mt < 2; mt++) {
        int row0 = (batch * 128 + (blockIdx.y & 127)) * 128 + wm + mt * 16 + (lane >> 2);
        // row within full output = batch*NB + m0 + ...; compute directly:
        int row = batch * NB + m0 + wm + mt * 16 + (lane >> 2);
        (void)row0;
#pragma unroll
        for (int nt = 0; nt < NT; nt++) {
            int col = n0 + wn + nt * 8 + (lane & 3) * 2;
            float b0v = bias[col], b1v = bias[col + 1];
            float x0 = acc[mt][nt][0] + b0v, x1 = acc[mt][nt][1] + b1v;
            float x2 = acc[mt][nt][2] + b0v, x3 = acc[mt][nt][3] + b1v;
            if (act) { x0 = geluf(x0); x1 = geluf(x1); x2 = geluf(x2); x3 = geluf(x3); }
            if (OUTBF) {
                __nv_bfloat16* C = (__nv_bfloat16*)Cv;
                *reinterpret_cast<__nv_bfloat162*>(C + (size_t)row * N + col) =
                    __floats2bfloat162_rn(x0, x1);
                *reinterpret_cast<__nv_bfloat162*>(C + (size_t)(row + 8) * N + col) =
                    __floats2bfloat162_rn(x2, x3);
            } else {
                float* C = (float*)Cv;
                *reinterpret_cast<float2*>(C + (size_t)row * N + col)       = make_float2(x0, x1);
                *reinterpret_cast<float2*>(C + (size_t)(row + 8) * N + col) = make_float2(x2, x3);
            }
        }
    }
}

// ================= precise 3xTF32 GEMM (info path only) =================
template<int BN>
__global__ void __launch_bounds__(256, 2) gemm_tf32p(
    APtrs A, int Ktot, const float* __restrict__ Wt, int N,
    const float* __restrict__ bias, float* __restrict__ C, int act)
{
    constexpr int AW = 36;
    constexpr int ABYTES = 128 * AW * 4;
    constexpr int BBYTES = BN * AW * 4;
    constexpr int STG = ABYTES + BBYTES;
    constexpr int NT = BN / 16;

    extern __shared__ char smem[];
    const int t = threadIdx.x, lane = t & 31, wid = t >> 5;
    const int batch = blockIdx.y >> 7;
    const int m0 = (blockIdx.y & 127) * 128;
    const int n0 = blockIdx.x * BN;
    const int wm = (wid & 3) * 32;
    const int wn = (wid >> 2) * (BN / 2);

    const float* A1 = A.p[batch];
    C += (size_t)batch * NB * N;

    const uint32_t sbase = smem_u32(smem);
    const uint32_t a_addr0 = sbase + (uint32_t)(((wm + (lane & 15)) * AW + (lane >> 4) * 4) * 4);
    const int grp = lane >> 3;
    const int b_r = (lane & 7) + ((grp >= 2) ? 8 : 0);
    const uint32_t b_addr0 = sbase + ABYTES + (uint32_t)(((wn + b_r) * AW + (grp & 1) * 4) * 4);

    float acc[2][NT][4];
#pragma unroll
    for (int i = 0; i < 2; i++)
#pragma unroll
        for (int j = 0; j < NT; j++)
#pragma unroll
            for (int q = 0; q < 4; q++) acc[i][j][q] = 0.0f;

    auto load_chunk = [&](int c) {
        const int stg = c % 3;
        uint32_t sA = sbase + stg * STG;
#pragma unroll
        for (int i = 0; i < 4; i++) {
            int idx = t + i * 256, r = idx >> 3, c4 = idx & 7;
            CP_ASYNC16(sA + (uint32_t)(r * AW + c4 * 4) * 4,
                       A1 + (size_t)(m0 + r) * Ktot + c * 32 + c4 * 4);
        }
        uint32_t sB = sA + ABYTES;
#pragma unroll
        for (int i = 0; i < BN / 32; i++) {
            int idx = t + i * 256, r = idx >> 3, c4 = idx & 7;
            CP_ASYNC16(sB + (uint32_t)(r * AW + c4 * 4) * 4,
                       Wt + (size_t)(n0 + r) * Ktot + c * 32 + c4 * 4);
        }
        CP_COMMIT();
    };

    const int NC = Ktot >> 5;
    load_chunk(0);
    if (NC > 1) load_chunk(1);

    for (int c = 0; c < NC; c++) {
        if (c + 1 < NC) { asm volatile("cp.async.wait_group 1;" ::: "memory"); }
        else            { asm volatile("cp.async.wait_group 0;" ::: "memory"); }
        __syncthreads();
        if (c + 2 < NC) load_chunk(c + 2);

        const uint32_t aa = a_addr0 + (c % 3) * STG;
        const uint32_t bb = b_addr0 + (c % 3) * STG;
#pragma unroll
        for (int kk = 0; kk < 4; kk++) {
            uint32_t Ah[2][4], Al[2][4];
            LDSM4(Ah[0], aa + kk * 32);
            LDSM4(Ah[1], aa + 16 * AW * 4 + kk * 32);
#pragma unroll
            for (int mt = 0; mt < 2; mt++)
#pragma unroll
                for (int q = 0; q < 4; q++) split_tf32(Ah[mt][q], Ah[mt][q], Al[mt][q]);
#pragma unroll
            for (int np = 0; np < NT / 2; np++) {
                uint32_t B4[4], Bh[4], Bl[4];
                LDSM4(B4, bb + np * 16 * AW * 4 + kk * 32);
#pragma unroll
                for (int q = 0; q < 4; q++) split_tf32(B4[q], Bh[q], Bl[q]);
#pragma unroll
                for (int mt = 0; mt < 2; mt++) {
                    mma_tf(acc[mt][2 * np],     Ah[mt], Bh[0], Bh[1]);
                    mma_tf(acc[mt][2 * np],     Ah[mt], Bl[0], Bl[1]);
                    mma_tf(acc[mt][2 * np],     Al[mt], Bh[0], Bh[1]);
                    mma_tf(acc[mt][2 * np + 1], Ah[mt], Bh[2], Bh[3]);
                    mma_tf(acc[mt][2 * np + 1], Ah[mt], Bl[2], Bl[3]);
                    mma_tf(acc[mt][2 * np + 1], Al[mt], Bh[2], Bh[3]);
                }
            }
        }
    }

#pragma unroll
    for (int mt = 0; mt < 2; mt++) {
        int row = m0 + wm + mt * 16 + (lane >> 2);
#pragma unroll
        for (int nt = 0; nt < NT; nt++) {
            int col = n0 + wn + nt * 8 + (lane & 3) * 2;
            float b0v = bias[col], b1v = bias[col + 1];
            float x0 = acc[mt][nt][0] + b0v, x1 = acc[mt][nt][1] + b1v;
            float x2 = acc[mt][nt][2] + b0v, x3 = acc[mt][nt][3] + b1v;
            if (act) { x0 = geluf(x0); x1 = geluf(x1); x2 = geluf(x2); x3 = geluf(x3); }
            *reinterpret_cast<float2*>(C + (size_t)row * N + col)       = make_float2(x0, x1);
            *reinterpret_cast<float2*>(C + (size_t)(row + 8) * N + col) = make_float2(x2, x3);
        }
    }
}

// ---------------- feature fp32 -> bf16 ----------------
__global__ void cvt_bf_k(const float4* __restrict__ s0, const float4* __restrict__ s1,
                         const float4* __restrict__ s2, const float4* __restrict__ s3,
                         __nv_bfloat16* __restrict__ d)
{
    int i = blockIdx.x * blockDim.x + threadIdx.x;      // over 4 * NB*768/4
    const int per = NB * 768 / 4;
    if (i >= 4 * per) return;
    int f = i / per, j = i - f * per;
    const float4* s = (f == 0 ? s0 : f == 1 ? s1 : f == 2 ? s2 : s3);
    float4 v = s[j];
    __nv_bfloat162* o = reinterpret_cast<__nv_bfloat162*>(d + (size_t)f * NB * 768 + (size_t)j * 4);
    o[0] = __floats2bfloat162_rn(v.x, v.y);
    o[1] = __floats2bfloat162_rn(v.z, v.w);
}

// ---------------- weight transpose [K,N] -> [N,K] (bf16 + fp32 variants) ----------------
__global__ void transpose_bf_k(const float* __restrict__ s, __nv_bfloat16* __restrict__ d, int K, int N) {
    __shared__ float tile[32][33];
    int n = blockIdx.x * 32 + threadIdx.x;
    int k = blockIdx.y * 32 + threadIdx.y;
#pragma unroll
    for (int i = 0; i < 32; i += 8) tile[threadIdx.y + i][threadIdx.x] = s[(size_t)(k + i) * N + n];
    __syncthreads();
    int n2 = blockIdx.x * 32 + threadIdx.y;
    int k2 = blockIdx.y * 32 + threadIdx.x;
#pragma unroll
    for (int i = 0; i < 32; i += 8)
        d[(size_t)(n2 + i) * K + k2] = __float2bfloat16(tile[threadIdx.x][threadIdx.y + i]);
}
__global__ void transpose_k(const float* __restrict__ s, float* __restrict__ d, int K, int N) {
    __shared__ float tile[32][33];
    int n = blockIdx.x * 32 + threadIdx.x;
    int k = blockIdx.y * 32 + threadIdx.y;
#pragma unroll
    for (int i = 0; i < 32; i += 8) tile[threadIdx.y + i][threadIdx.x] = s[(size_t)(k + i) * N + n];
    __syncthreads();
    int n2 = blockIdx.x * 32 + threadIdx.y;
    int k2 = blockIdx.y * 32 + threadIdx.x;
#pragma unroll
    for (int i = 0; i < 32; i += 8) d[(size_t)(n2 + i) * K + k2] = tile[threadIdx.x][threadIdx.y + i];
}

// ---------------- final dot head (fp32 H) ----------------
__global__ void dot_head_k(const float* __restrict__ Hin, int K, int rows,
                           const float* __restrict__ w, const float* __restrict__ b,
                           float* __restrict__ outrow)
{
    int gw = (blockIdx.x * blockDim.x + threadIdx.x) >> 5;
    int lane = threadIdx.x & 31;
    if (gw >= rows) return;
    const float* row = Hin + (size_t)gw * K;
    float s = 0.f;
    for (int k = lane * 4; k < K; k += 128) {
        float4 v = *reinterpret_cast<const float4*>(row + k);
        float4 wv = *reinterpret_cast<const float4*>(w + k);
        s += v.x * wv.x + v.y * wv.y + v.z * wv.z + v.w * wv.w;
    }
#pragma unroll
    for (int o = 16; o; o >>= 1) s += __shfl_xor_sync(0xffffffffu, s, o);
    if (lane == 0) outrow[gw] = sigf(s + b[0]);
}

// ---------------- geometric quality (rows 0..3) + norms ----------------
__global__ void rowstats_k(const float* __restrict__ f0, const float* __restrict__ f1,
                           const float* __restrict__ f2, const float* __restrict__ f3,
                           float* __restrict__ out)
{
    int gw = (blockIdx.x * blockDim.x + threadIdx.x) >> 5;
    int lane = threadIdx.x & 31;
    if (gw >= 4 * NB) return;
    int feat = gw >> 14;
    int m = gw & (NB - 1);
    const float* f = (feat == 0 ? f0 : feat == 1 ? f1 : feat == 2 ? f2 : f3) + (size_t)m * HD;
    double sum = 0.0, ssq = 0.0;
    int cnt = 0;
    for (int k = lane * 4; k < HD; k += 128) {
        float4 v = *reinterpret_cast<const float4*>(f + k);
        sum += (double)v.x + v.y + v.z + v.w;
        ssq += (double)v.x * v.x + (double)v.y * v.y + (double)v.z * v.z + (double)v.w * v.w;
        cnt += (fabsf(v.x) > 0.01f) + (fabsf(v.y) > 0.01f) + (fabsf(v.z) > 0.01f) + (fabsf(v.w) > 0.01f);
    }
#pragma unroll
    for (int o = 16; o; o >>= 1) {
        sum += __shfl_xor_sync(0xffffffffu, sum, o);
        ssq += __shfl_xor_sync(0xffffffffu, ssq, o);
        cnt += __shfl_xor_sync(0xffffffffu, cnt, o);
    }
    if (lane == 0) {
        float n = (float)sqrt(ssq);
        float nq = sigf((n - 1.0f) * 2.0f);
        float sp = cnt * (1.0f / 768.0f);
        double var = (ssq - sum * sum / 768.0) / 767.0;
        if (var < 0.0) var = 0.0;
        float sq = sigf((float)sqrt(var) * 10.0f - 1.0f);
        out[feat * NB + m] = (nq + sp + sq) * (1.0f / 3.0f);
        if (feat < 2) g_norm[feat * NB + m] = n;
    }
}

// ---------------- information quality final (2*NB rows) ----------------
__global__ void info_final_k(const float* __restrict__ enc, float* __restrict__ outrow)
{
    int gw = (blockIdx.x * blockDim.x + threadIdx.x) >> 5;
    int lane = threadIdx.x & 31;
    if (gw >= 2 * NB) return;
    const float* e = enc + (size_t)gw * 64;
    float x0 = e[lane], x1 = e[lane + 32];
    int d0 = (int)rintf(sigf(x0) * 10.0f);
    int d1 = (int)rintf(sigf(x1) * 10.0f);
    float ent = 0.f;
#pragma unroll
    for (int b = 0; b < 11; b++) {
        int c = __popc(__ballot_sync(0xffffffffu, d0 == b)) +
                __popc(__ballot_sync(0xffffffffu, d1 == b));
        if (c > 0) {
            float p = c * (1.0f / 64.0f);
            ent -= p * logf(p + 1e-8f);
        }
    }
    if (lane == 0) {
        float eq = sigf(ent - 2.0f);
        float n = g_norm[gw];
        float cq = (n > 0.01f) ? (1.0f / 768.0f) : 0.0f;
        float t = n / fmaxf(n, 1e-12f);
        float dq = sigf(t * t - 0.5f);
        outrow[gw] = (eq + cq + dq) * (1.0f / 3.0f);
    }
}

__global__ void overall_k(float* __restrict__ out)
{
    int i = blockIdx.x * blockDim.x + threadIdx.x;
    if (i >= NB) return;
    float v = out[0 * NB + i] + out[1 * NB + i] + out[4 * NB + i] + out[5 * NB + i] +
              out[7 * NB + i] + 0.5f * (out[8 * NB + i] + out[9 * NB + i]);
    out[17 * NB + i] = v * (1.0f / 6.0f);
}

// ---------------- host ----------------
template<int BN, bool OUTBF>
static void launch_bf(APtrsB A, int nb, int Khalf, int Ktot,
                      const __nv_bfloat16* Wt, int N, const float* bias, void* C, int act)
{
    int smemB = 3 * (128 + BN) * 40 * 2;
    cudaFuncSetAttribute(gemm_bf16<BN, OUTBF>, cudaFuncAttributeMaxDynamicSharedMemorySize, smemB);
    dim3 g(N / BN, nb * 128);
    gemm_bf16<BN, OUTBF><<<g, 256, smemB>>>(A, Khalf, Ktot, Wt, N, bias, C, act);
}
template<int BN>
static void launch_tp(APtrs A, int nb, int Ktot, const float* Wt, int N,
                      const float* bias, float* C, int act)
{
    int smemB = 3 * (128 + BN) * 36 * 4;
    cudaFuncSetAttribute(gemm_tf32p<BN>, cudaFuncAttributeMaxDynamicSharedMemorySize, smemB);
    dim3 g(N / BN, nb * 128);
    gemm_tf32p<BN><<<g, 256, smemB>>>(A, Ktot, Wt, N, bias, C, act);
}
static void trbf(const float* s, __nv_bfloat16* d, int K, int N) {
    dim3 b(32, 8), g(N / 32, K / 32);
    transpose_bf_k<<<g, b>>>(s, d, K, N);
}
static void tr(const float* s, float* d, int K, int N) {
    dim3 b(32, 8), g(N / 32, K / 32);
    transpose_k<<<g, b>>>(s, d, K, N);
}

extern "C" void kernel_launch(void* const* d_in, const int* in_sizes, int n_in,
                              void* d_out, int out_size)
{
    const float* img  = (const float*)d_in[0];
    const float* txt  = (const float*)d_in[1];
    const float* eimg = (const float*)d_in[2];
    const float* etxt = (const float*)d_in[3];
    const float* info_w1 = (const float*)d_in[5];
    const float* info_b1 = (const float*)d_in[6];
    const float* info_w2 = (const float*)d_in[7];
    const float* info_b2 = (const float*)d_in[8];
    const float* imp_w1  = (const float*)d_in[9];
    const float* imp_b1  = (const float*)d_in[10];
    const float* imp_w2  = (const float*)d_in[11];
    const float* imp_b2  = (const float*)d_in[12];
    const float* disc_w1 = (const float*)d_in[13];
    const float* disc_b1 = (const float*)d_in[14];
    const float* disc_w2 = (const float*)d_in[15];
    const float* disc_b2 = (const float*)d_in[16];
    const float* disc_w3 = (const float*)d_in[17];
    const float* disc_b3 = (const float*)d_in[18];
    const float* cons_w1 = (const float*)d_in[19];
    const float* cons_b1 = (const float*)d_in[20];
    const float* cons_w2 = (const float*)d_in[21];
    const float* cons_b2 = (const float*)d_in[22];
    const float* cons_w3 = (const float*)d_in[23];
    const float* cons_b3 = (const float*)d_in[24];
    const float* diff_w1 = (const float*)d_in[25];
    const float* diff_b1 = (const float*)d_in[26];
    const float* diff_w2 = (const float*)d_in[27];
    const float* diff_b2 = (const float*)d_in[28];
    const float* diff_w3 = (const float*)d_in[29];
    const float* diff_b3 = (const float*)d_in[30];

    float* out = (float*)d_out;

    __nv_bfloat16 *featbf, *scrAbf, *scrCbf;
    __nv_bfloat16 *w_imp1, *w_disc1, *w_disc2, *w_cons1, *w_cons2, *w_diff1, *w_diff2;
    float *scrB, *scrC, *scrD, *w_i1, *w_i2;
    cudaGetSymbolAddress((void**)&featbf, g_featbf);
    cudaGetSymbolAddress((void**)&scrAbf, g_scrAbf);
    cudaGetSymbolAddress((void**)&scrCbf, g_scrCbf);
    cudaGetSymbolAddress((void**)&scrB, g_scrB);
    cudaGetSymbolAddress((void**)&scrC, g_scrC);
    cudaGetSymbolAddress((void**)&scrD, g_scrD);
    cudaGetSymbolAddress((void**)&w_imp1, g_w_imp1);
    cudaGetSymbolAddress((void**)&w_disc1, g_w_disc1);
    cudaGetSymbolAddress((void**)&w_disc2, g_w_disc2);
    cudaGetSymbolAddress((void**)&w_cons1, g_w_cons1);
    cudaGetSymbolAddress((void**)&w_cons2, g_w_cons2);
    cudaGetSymbolAddress((void**)&w_diff1, g_w_diff1);
    cudaGetSymbolAddress((void**)&w_diff2, g_w_diff2);
    cudaGetSymbolAddress((void**)&w_i1, g_w_info1);
    cudaGetSymbolAddress((void**)&w_i2, g_w_info2);

    const __nv_bfloat16* bimg  = featbf;
    const __nv_bfloat16* btxt  = featbf + (size_t)NB * 768;
    const __nv_bfloat16* beimg = featbf + (size_t)2 * NB * 768;
    const __nv_bfloat16* betxt = featbf + (size_t)3 * NB * 768;

    // conversions + weight transposes
    cvt_bf_k<<<(4 * NB * 768 / 4 + 255) / 256, 256>>>(
        (const float4*)img, (const float4*)txt, (const float4*)eimg, (const float4*)etxt, featbf);
    trbf(imp_w1,  w_imp1,  768, 384);
    trbf(disc_w1, w_disc1, 768, 256);
    trbf(disc_w2, w_disc2, 256, 64);
    trbf(cons_w1, w_cons1, 1536, 768);
    trbf(cons_w2, w_cons2, 768, 384);
    trbf(diff_w1, w_diff1, 1536, 768);
    trbf(diff_w2, w_diff2, 768, 384);
    tr(info_w1, w_i1, 768, 256);
    tr(info_w2, w_i2, 256, 64);

    // geometric (rows 0..3) + norms
    rowstats_k<<<(4 * NB) / 8, 256>>>(img, txt, eimg, etxt, out);

    // information (rows 4,5) — 3xTF32 precise, batched 2
    {
        APtrs a = {{ img, txt, nullptr, nullptr }};
        launch_tp<128>(a, 2, 768, w_i1, 256, info_b1, scrC, 1);
        APtrs a2 = {{ scrC, scrC + (size_t)NB * 256, nullptr, nullptr }};
        launch_tp<64>(a2, 2, 256, w_i2, 64, info_b2, scrD, 0);
        info_final_k<<<(2 * NB) / 8, 256>>>(scrD, out + 4 * NB);
    }

    // importance (rows 8..11) — batched 4
    {
        APtrsB a = {{ bimg, btxt, beimg, betxt }};
        launch_bf<128, false>(a, 4, 768, 768, w_imp1, 384, imp_b1, scrB, 1);
        dot_head_k<<<(4 * NB) / 8, 256>>>(scrB, 384, 4 * NB, imp_w2, imp_b2, out + 8 * NB);
    }

    // discriminator (rows 12..15) — batched 4: img, eimg, txt, etxt
    {
        APtrsB a = {{ bimg, beimg, btxt, betxt }};
        launch_bf<128, true>(a, 4, 768, 768, w_disc1, 256, disc_b1, scrCbf, 1);
        APtrsB a2 = {{ scrCbf, scrCbf + (size_t)NB * 256, scrCbf + (size_t)2 * NB * 256,
                       scrCbf + (size_t)3 * NB * 256 }};
        launch_bf<64, false>(a2, 4, 256, 256, w_disc2, 64, disc_b2, scrD, 1);
        dot_head_k<<<(4 * NB) / 8, 256>>>(scrD, 64, 4 * NB, disc_w3, disc_b3, out + 12 * NB);
    }

    // consistency (rows 6,7) — batched 2 concat pairs
    {
        APtrsB a = {{ bimg, btxt, beimg, betxt }};
        launch_bf<128, true>(a, 2, 768, 1536, w_cons1, 768, cons_b1, scrAbf, 1);
        APtrsB a2 = {{ scrAbf, scrAbf + (size_t)NB * 768, nullptr, nullptr }};
        launch_bf<128, false>(a2, 2, 768, 768, w_cons2, 384, cons_b2, scrB, 1);
        dot_head_k<<<(2 * NB) / 8, 256>>>(scrB, 384, 2 * NB, cons_w3, cons_b3, out + 6 * NB);
    }

    // difficulty (row 16) — single concat pair
    {
        APtrsB a = {{ beimg, betxt, nullptr, nullptr }};
        launch_bf<128, true>(a, 1, 768, 1536, w_diff1, 768, diff_b1, scrAbf, 1);
        APtrsB a2 = {{ scrAbf, nullptr, nullptr, nullptr }};
        launch_bf<128, false>(a2, 1, 768, 768, w_diff2, 384, diff_b2, scrB, 1);
        dot_head_k<<<NB / 8, 256>>>(scrB, 384, NB, diff_w3, diff_b3, out + 16 * NB);
    }

    // overall (row 17)
    overall_k<<<NB / 256, 256>>>(out);
}